// round 3
// baseline (speedup 1.0000x reference)
#include <cuda_runtime.h>
#include <cuda_bf16.h>
#include <cstdint>

// ============================================================================
// BinaryLinearWscales (GB300, compiled via compute_103 -> no tcgen05).
//   out[m,n] = wscale[n] * (x @ sign(W)^T)[m,n] + wbias[n] * rowsum(x)[m]
// GEMM as 2-level int8: x ~= alpha_m * (q1 + q2/254), sign(W) exact in s8.
// mma.sync.m16n8k32.s8 with s32 accum; cp.async.bulk 3-stage pipeline.
// M = N = K = 4096.
// ============================================================================

// ---------------- device scratch (pre-swizzled tiled s8) --------------------
// Layout: [tile(128 rows)][kchunk(128 bytes)] -> 16KB tile, SW128 swizzled.
__device__ __align__(16384) int8_t g_a0[16777216];   // 16 MB: q1 of x
__device__ __align__(16384) int8_t g_a1[16777216];   // 16 MB: q2 of x
__device__ __align__(16384) int8_t g_b [16777216];   // 16 MB: sign(W)
__device__ float g_scale [4096];                     // alpha_m
__device__ float g_rowsum[4096];

// ---------------- PTX helpers ------------------------------------------------
static __device__ __forceinline__ uint32_t smem_u32(const void* p) {
    uint32_t a;
    asm("{ .reg .u64 t; cvta.to.shared.u64 t, %1; cvt.u32.u64 %0, t; }" : "=r"(a) : "l"(p));
    return a;
}

#define MBARRIER_INIT(addr, cnt) \
    asm volatile("mbarrier.init.shared.b64 [%0], %1;" :: "r"((uint32_t)(addr)), "r"((uint32_t)(cnt)) : "memory")

#define MBARRIER_EXPECT_TX(addr, bytes) \
    asm volatile("mbarrier.arrive.expect_tx.shared.b64 _, [%0], %1;" :: "r"((uint32_t)(addr)), "r"((uint32_t)(bytes)) : "memory")

#define MBARRIER_ARRIVE(addr) \
    asm volatile("mbarrier.arrive.shared.b64 _, [%0];" :: "r"((uint32_t)(addr)) : "memory")

#define MBARRIER_WAIT_PARITY(mbar_addr, parity) do {                               \
    uint32_t _m = (uint32_t)(mbar_addr); uint32_t _p = (uint32_t)(parity);         \
    uint32_t _d;                                                                    \
    asm volatile("{\n\t.reg .pred p;\n\t"                                           \
        "mbarrier.try_wait.parity.acquire.cta.shared::cta.b64 p, [%1], %2;\n\t"     \
        "selp.b32 %0, 1, 0, p;\n\t}" : "=r"(_d) : "r"(_m), "r"(_p) : "memory");     \
    if (!_d) {                                                                      \
        asm volatile("{\n\t.reg .pred P1;\n\t"                                      \
        "WL_%=:\n\t"                                                                \
        "mbarrier.try_wait.parity.acquire.cta.shared::cta.b64 P1, [%0], %1, 0x989680;\n\t" \
        "@P1 bra.uni WD_%=;\n\t"                                                    \
        "bra.uni WL_%=;\n\t"                                                        \
        "WD_%=:\n\t}" :: "r"(_m), "r"(_p) : "memory");                              \
    }                                                                               \
} while (0)

#define MBARRIER_WAIT_PARITY_RELAXED(mbar_addr, parity) do {                       \
    uint32_t _m = (uint32_t)(mbar_addr); uint32_t _p = (uint32_t)(parity);         \
    uint32_t _d;                                                                    \
    asm volatile("{\n\t.reg .pred p;\n\t"                                           \
        "mbarrier.try_wait.parity.relaxed.cta.shared::cta.b64 p, [%1], %2, 0x989680;\n\t" \
        "selp.b32 %0, 1, 0, p;\n\t}" : "=r"(_d) : "r"(_m), "r"(_p) : "memory");     \
    if (!_d) {                                                                      \
        asm volatile("{\n\t.reg .pred P1;\n\t"                                      \
        "WL_%=:\n\t"                                                                \
        "mbarrier.try_wait.parity.relaxed.cta.shared::cta.b64 P1, [%0], %1, 0x989680;\n\t" \
        "@P1 bra.uni WD_%=;\n\t"                                                    \
        "bra.uni WL_%=;\n\t"                                                        \
        "WD_%=:\n\t}" :: "r"(_m), "r"(_p) : "memory");                              \
    }                                                                               \
} while (0)

static __device__ __forceinline__ void bulk_g2s(uint32_t dst, const void* src,
                                                uint32_t bytes, uint32_t mbar) {
    asm volatile(
        "cp.async.bulk.shared::cluster.global.mbarrier::complete_tx::bytes [%0], [%1], %2, [%3];"
        :: "r"(dst), "l"(src), "r"(bytes), "r"(mbar) : "memory");
}

static __device__ __forceinline__ void ldsm4(uint32_t* r, uint32_t addr) {
    asm volatile("ldmatrix.sync.aligned.m8n8.x4.shared.b16 {%0,%1,%2,%3}, [%4];"
        : "=r"(r[0]), "=r"(r[1]), "=r"(r[2]), "=r"(r[3]) : "r"(addr));
}

static __device__ __forceinline__ void imma(int* d, const uint32_t* a,
                                            uint32_t b0, uint32_t b1) {
    asm volatile(
        "mma.sync.aligned.m16n8k32.row.col.s32.s8.s8.s32 "
        "{%0,%1,%2,%3}, {%4,%5,%6,%7}, {%8,%9}, {%0,%1,%2,%3};"
        : "+r"(d[0]), "+r"(d[1]), "+r"(d[2]), "+r"(d[3])
        : "r"(a[0]), "r"(a[1]), "r"(a[2]), "r"(a[3]), "r"(b0), "r"(b1));
}

// ---------------- geometry ----------------------------------------------------
static constexpr int      NCHUNK      = 32;       // 4096 / 128
static constexpr uint32_t TILE_BYTES  = 16384;    // 128 rows x 128 k-bytes
static constexpr int      STAGES      = 3;
static constexpr uint32_t STAGE_BYTES = 3 * TILE_BYTES;   // A0 + A1 + B = 48KB
static constexpr uint32_t OFF_FULL    = 0;        // 3 x 8B
static constexpr uint32_t OFF_EMPTY   = 64;       // 3 x 8B
static constexpr uint32_t OFF_STAGE   = 1024;
static constexpr uint32_t SMEM_DYN    = OFF_STAGE + STAGES * STAGE_BYTES;  // 148480

// ---------------- prologue: quantize x (2 s8 levels) + rowsum + scale --------
__global__ void __launch_bounds__(256) prep_x_kernel(const float* __restrict__ x) {
    const int m = blockIdx.x;
    const int tid = threadIdx.x;
    const float4* row = (const float4*)(x + (size_t)m * 4096);
    float4 v[4];
    #pragma unroll
    for (int i = 0; i < 4; i++) v[i] = row[tid * 4 + i];

    float mx = 0.f, sm = 0.f;
    #pragma unroll
    for (int i = 0; i < 4; i++) {
        mx = fmaxf(mx, fmaxf(fmaxf(fabsf(v[i].x), fabsf(v[i].y)),
                             fmaxf(fabsf(v[i].z), fabsf(v[i].w))));
        sm += (v[i].x + v[i].y) + (v[i].z + v[i].w);
    }
    __shared__ float smax[256], ssum[256];
    smax[tid] = mx; ssum[tid] = sm;
    __syncthreads();
    for (int s = 128; s > 0; s >>= 1) {
        if (tid < s) {
            smax[tid] = fmaxf(smax[tid], smax[tid + s]);
            ssum[tid] += ssum[tid + s];
        }
        __syncthreads();
    }
    const float maxv = smax[0];
    const float inv  = (maxv > 0.f) ? 127.f / maxv : 0.f;

    uint32_t p1[4], p2[4];
    #pragma unroll
    for (int i = 0; i < 4; i++) {
        float e[4] = {v[i].x, v[i].y, v[i].z, v[i].w};
        uint32_t w1 = 0, w2 = 0;
        #pragma unroll
        for (int b = 0; b < 4; b++) {
            float r0 = e[b] * inv;
            int q1 = __float2int_rn(r0);
            int q2 = __float2int_rn((r0 - (float)q1) * 254.f);
            w1 |= (uint32_t)(q1 & 0xff) << (8 * b);
            w2 |= (uint32_t)(q2 & 0xff) << (8 * b);
        }
        p1[i] = w1; p2[i] = w2;
    }
    // tile addr: [mtile][kchunk][swizzled 16KB]
    const uint32_t inrow = (uint32_t)((tid & 7) * 16);
    const uint32_t swzc  = inrow ^ (uint32_t)((m & 7) << 4);
    const size_t off = ((size_t)(m >> 7) * 32 + (size_t)(tid >> 3)) * TILE_BYTES
                     + (size_t)((m & 127) * 128) + swzc;
    *(uint4*)((char*)g_a0 + off) = make_uint4(p1[0], p1[1], p1[2], p1[3]);
    *(uint4*)((char*)g_a1 + off) = make_uint4(p2[0], p2[1], p2[2], p2[3]);
    if (tid == 0) {
        g_scale[m]  = (maxv > 0.f) ? maxv / 127.f : 0.f;
        g_rowsum[m] = ssum[0];
    }
}

// ---------------- prologue: sign(W) as s8 -------------------------------------
__global__ void __launch_bounds__(256) prep_w_kernel(const float* __restrict__ w) {
    const int n = blockIdx.x;
    const int tid = threadIdx.x;
    const float4* row = (const float4*)(w + (size_t)n * 4096);
    uint32_t p[4];
    #pragma unroll
    for (int i = 0; i < 4; i++) {
        float4 v = row[tid * 4 + i];
        float e[4] = {v.x, v.y, v.z, v.w};
        uint32_t wq = 0;
        #pragma unroll
        for (int b = 0; b < 4; b++) {
            int q = (e[b] > 0.f) ? 1 : ((e[b] < 0.f) ? -1 : 0);
            wq |= (uint32_t)(q & 0xff) << (8 * b);
        }
        p[i] = wq;
    }
    const uint32_t inrow = (uint32_t)((tid & 7) * 16);
    const uint32_t swzc  = inrow ^ (uint32_t)((n & 7) << 4);
    const size_t off = ((size_t)(n >> 7) * 32 + (size_t)(tid >> 3)) * TILE_BYTES
                     + (size_t)((n & 127) * 128) + swzc;
    *(uint4*)((char*)g_b + off) = make_uint4(p[0], p[1], p[2], p[3]);
}

// ---------------- main GEMM ----------------------------------------------------
// grid (32 ntile, 32 mtile), 288 threads: warps 0-7 compute, warp 8 = producer.
__global__ void __launch_bounds__(288, 1)
gemm_kernel(const float* __restrict__ wscale, const float* __restrict__ wbias,
            float* __restrict__ out) {
    extern __shared__ __align__(1024) char smem[];
    const uint32_t sb = smem_u32(smem);
    const int tid = threadIdx.x;
    const int wid = tid >> 5;
    const int lane = tid & 31;
    const int ntile = blockIdx.x;
    const int mtile = blockIdx.y;

    if (tid == 0) {
        #pragma unroll
        for (int s = 0; s < STAGES; s++) {
            MBARRIER_INIT(sb + OFF_FULL  + 8u * s, 1);
            MBARRIER_INIT(sb + OFF_EMPTY + 8u * s, 8);
        }
    }
    __syncthreads();

    if (wid == 8) {
        // ---------------- producer ----------------
        if (lane == 0) {
            const char* pa0 = (const char*)g_a0 + (size_t)mtile * (32u * TILE_BYTES);
            const char* pa1 = (const char*)g_a1 + (size_t)mtile * (32u * TILE_BYTES);
            const char* pb  = (const char*)g_b  + (size_t)ntile * (32u * TILE_BYTES);
            int st = 0, ph = 1;
            for (int ch = 0; ch < NCHUNK; ch++) {
                MBARRIER_WAIT_PARITY_RELAXED(sb + OFF_EMPTY + 8u * st, ph);
                uint32_t fb = sb + OFF_FULL + 8u * st;
                MBARRIER_EXPECT_TX(fb, STAGE_BYTES);
                uint32_t dst = sb + OFF_STAGE + (uint32_t)st * STAGE_BYTES;
                size_t co = (size_t)ch * TILE_BYTES;
                bulk_g2s(dst,                  pa0 + co, TILE_BYTES, fb);
                bulk_g2s(dst + TILE_BYTES,     pa1 + co, TILE_BYTES, fb);
                bulk_g2s(dst + 2 * TILE_BYTES, pb  + co, TILE_BYTES, fb);
                if (++st == STAGES) { st = 0; ph ^= 1; }
            }
        }
        return;
    }

    // ---------------- consumers: 8 warps, 4(M) x 2(N), warp tile 32x64 --------
    const int mw = wid >> 1;          // 0..3
    const int nw = wid & 1;           // 0..1
    const int rA = lane & 15;
    const uint32_t hb = (uint32_t)((lane >> 4) * 16);
    const uint32_t ph_sw = (uint32_t)((rA & 7) << 4);

    // per-lane row byte offsets within a 16KB tile
    uint32_t rowA[2], rowB[4];
    #pragma unroll
    for (int t = 0; t < 2; t++) rowA[t] = (uint32_t)((mw * 32 + t * 16 + rA) * 128);
    #pragma unroll
    for (int j = 0; j < 4; j++) rowB[j] = (uint32_t)((nw * 64 + j * 16 + rA) * 128);
    uint32_t colx[4];
    #pragma unroll
    for (int ks = 0; ks < 4; ks++) colx[ks] = ((uint32_t)(ks * 32) + hb) ^ ph_sw;

    int acc0[2][8][4];   // level-0 accumulators
    int acc1[2][8][4];   // level-1 accumulators
    #pragma unroll
    for (int t = 0; t < 2; t++)
        #pragma unroll
        for (int u = 0; u < 8; u++)
            #pragma unroll
            for (int i = 0; i < 4; i++) { acc0[t][u][i] = 0; acc1[t][u][i] = 0; }

    int st = 0, phc = 0;
    for (int ch = 0; ch < NCHUNK; ch++) {
        MBARRIER_WAIT_PARITY(sb + OFF_FULL + 8u * st, phc);
        const uint32_t SA0 = sb + OFF_STAGE + (uint32_t)st * STAGE_BYTES;
        const uint32_t SA1 = SA0 + TILE_BYTES;
        const uint32_t SB  = SA0 + 2 * TILE_BYTES;

        #pragma unroll
        for (int ks = 0; ks < 4; ks++) {
            uint32_t a0f[2][4], a1f[2][4], bf[4][4];
            #pragma unroll
            for (int t = 0; t < 2; t++) {
                ldsm4(a0f[t], SA0 + rowA[t] + colx[ks]);
                ldsm4(a1f[t], SA1 + rowA[t] + colx[ks]);
            }
            #pragma unroll
            for (int j = 0; j < 4; j++) ldsm4(bf[j], SB + rowB[j] + colx[ks]);

            #pragma unroll
            for (int t = 0; t < 2; t++) {
                #pragma unroll
                for (int j = 0; j < 4; j++) {
                    imma(acc0[t][2 * j],     a0f[t], bf[j][0], bf[j][2]);
                    imma(acc0[t][2 * j + 1], a0f[t], bf[j][1], bf[j][3]);
                    imma(acc1[t][2 * j],     a1f[t], bf[j][0], bf[j][2]);
                    imma(acc1[t][2 * j + 1], a1f[t], bf[j][1], bf[j][3]);
                }
            }
        }
        if (lane == 0) MBARRIER_ARRIVE(sb + OFF_EMPTY + 8u * st);
        if (++st == STAGES) { st = 0; phc ^= 1; }
    }

    // ---------------- epilogue ----------------
    const float inv254 = 1.f / 254.f;
    const int lg = lane >> 2;           // 0..7
    const int lc = (lane & 3) * 2;      // 0,2,4,6
    const int nbase = ntile * 128 + nw * 64 + lc;
    #pragma unroll
    for (int t = 0; t < 2; t++) {
        #pragma unroll
        for (int half = 0; half < 2; half++) {
            const int m = mtile * 128 + mw * 32 + t * 16 + lg + half * 8;
            const float alpha = g_scale[m];
            const float rs    = g_rowsum[m];
            float* orow = out + (size_t)m * 4096;
            const int i0 = half * 2, i1 = half * 2 + 1;
            #pragma unroll
            for (int u = 0; u < 8; u++) {
                const int n = nbase + u * 8;
                float v0 = (float)acc0[t][u][i0] + (float)acc1[t][u][i0] * inv254;
                float v1 = (float)acc0[t][u][i1] + (float)acc1[t][u][i1] * inv254;
                float2 o;
                o.x = __ldg(wscale + n)     * (alpha * v0) + __ldg(wbias + n)     * rs;
                o.y = __ldg(wscale + n + 1) * (alpha * v1) + __ldg(wbias + n + 1) * rs;
                *(float2*)(orow + n) = o;
            }
        }
    }
}

// ---------------- launch --------------------------------------------------------
extern "C" void kernel_launch(void* const* d_in, const int* in_sizes, int n_in,
                              void* d_out, int out_size) {
    (void)in_sizes; (void)n_in; (void)out_size;
    const float* x      = (const float*)d_in[0];   // [2,2048,4096]
    const float* weight = (const float*)d_in[1];   // [4096,4096]
    const float* wscale = (const float*)d_in[2];   // [4096,1]
    const float* wbias  = (const float*)d_in[3];   // [4096,1]
    float* out = (float*)d_out;

    cudaFuncSetAttribute(gemm_kernel, cudaFuncAttributeMaxDynamicSharedMemorySize,
                         (int)SMEM_DYN);

    prep_x_kernel<<<4096, 256>>>(x);
    prep_w_kernel<<<4096, 256>>>(weight);
    dim3 grid(32, 32);
    gemm_kernel<<<grid, 288, SMEM_DYN>>>(wscale, wbias, out);
}

// round 4
// speedup vs baseline: 1.0099x; 1.0099x over previous
#include <cuda_runtime.h>
#include <cuda_bf16.h>
#include <cstdint>

// ============================================================================
// BinaryLinearWscales (GB300, compute_103 -> mma.sync path, no tcgen05).
//   out[m,n] = wscale[n] * (x @ sign(W)^T)[m,n] + wbias[n] * rowsum(x)[m]
// GEMM as 2-level int8: x ~= alpha_m * (q1 + q2/254), sign(W) exact in s8.
// mma.sync.m16n8k32.s8, s32 accum. 16 compute warps (4Mx4N, 32x32 warp tile,
// both levels per warp -> 64 accum regs/thread, no spills).
// 4-stage cp.async.bulk pipeline, self-issued from warp 0 lane 0.
// ============================================================================

// ---------------- device scratch (pre-swizzled tiled s8) --------------------
// Layout: [tile(128 rows)][kchunk(128 bytes)] -> 16KB tile, SW128 swizzled.
__device__ __align__(16384) int8_t g_a0[16777216];   // 16 MB: q1 of x
__device__ __align__(16384) int8_t g_a1[16777216];   // 16 MB: q2 of x
__device__ __align__(16384) int8_t g_b [16777216];   // 16 MB: sign(W)
__device__ float g_scale [4096];
__device__ float g_rowsum[4096];

// ---------------- PTX helpers ------------------------------------------------
static __device__ __forceinline__ uint32_t smem_u32(const void* p) {
    uint32_t a;
    asm("{ .reg .u64 t; cvta.to.shared.u64 t, %1; cvt.u32.u64 %0, t; }" : "=r"(a) : "l"(p));
    return a;
}

#define MBARRIER_INIT(addr, cnt) \
    asm volatile("mbarrier.init.shared.b64 [%0], %1;" :: "r"((uint32_t)(addr)), "r"((uint32_t)(cnt)) : "memory")

#define MBARRIER_EXPECT_TX(addr, bytes) \
    asm volatile("mbarrier.arrive.expect_tx.shared.b64 _, [%0], %1;" :: "r"((uint32_t)(addr)), "r"((uint32_t)(bytes)) : "memory")

#define MBARRIER_ARRIVE(addr) \
    asm volatile("mbarrier.arrive.shared.b64 _, [%0];" :: "r"((uint32_t)(addr)) : "memory")

#define MBARRIER_WAIT_PARITY(mbar_addr, parity) do {                               \
    uint32_t _m = (uint32_t)(mbar_addr); uint32_t _p = (uint32_t)(parity);         \
    uint32_t _d;                                                                    \
    asm volatile("{\n\t.reg .pred p;\n\t"                                           \
        "mbarrier.try_wait.parity.acquire.cta.shared::cta.b64 p, [%1], %2;\n\t"     \
        "selp.b32 %0, 1, 0, p;\n\t}" : "=r"(_d) : "r"(_m), "r"(_p) : "memory");     \
    if (!_d) {                                                                      \
        asm volatile("{\n\t.reg .pred P1;\n\t"                                      \
        "WL_%=:\n\t"                                                                \
        "mbarrier.try_wait.parity.acquire.cta.shared::cta.b64 P1, [%0], %1, 0x989680;\n\t" \
        "@P1 bra.uni WD_%=;\n\t"                                                    \
        "bra.uni WL_%=;\n\t"                                                        \
        "WD_%=:\n\t}" :: "r"(_m), "r"(_p) : "memory");                              \
    }                                                                               \
} while (0)

#define MBARRIER_WAIT_PARITY_RELAXED(mbar_addr, parity) do {                       \
    uint32_t _m = (uint32_t)(mbar_addr); uint32_t _p = (uint32_t)(parity);         \
    uint32_t _d;                                                                    \
    asm volatile("{\n\t.reg .pred p;\n\t"                                           \
        "mbarrier.try_wait.parity.relaxed.cta.shared::cta.b64 p, [%1], %2, 0x989680;\n\t" \
        "selp.b32 %0, 1, 0, p;\n\t}" : "=r"(_d) : "r"(_m), "r"(_p) : "memory");     \
    if (!_d) {                                                                      \
        asm volatile("{\n\t.reg .pred P1;\n\t"                                      \
        "WL_%=:\n\t"                                                                \
        "mbarrier.try_wait.parity.relaxed.cta.shared::cta.b64 P1, [%0], %1, 0x989680;\n\t" \
        "@P1 bra.uni WD_%=;\n\t"                                                    \
        "bra.uni WL_%=;\n\t"                                                        \
        "WD_%=:\n\t}" :: "r"(_m), "r"(_p) : "memory");                              \
    }                                                                               \
} while (0)

static __device__ __forceinline__ void bulk_g2s(uint32_t dst, const void* src,
                                                uint32_t bytes, uint32_t mbar) {
    asm volatile(
        "cp.async.bulk.shared::cluster.global.mbarrier::complete_tx::bytes [%0], [%1], %2, [%3];"
        :: "r"(dst), "l"(src), "r"(bytes), "r"(mbar) : "memory");
}

static __device__ __forceinline__ void ldsm4(uint32_t* r, uint32_t addr) {
    asm volatile("ldmatrix.sync.aligned.m8n8.x4.shared.b16 {%0,%1,%2,%3}, [%4];"
        : "=r"(r[0]), "=r"(r[1]), "=r"(r[2]), "=r"(r[3]) : "r"(addr));
}

static __device__ __forceinline__ void imma(int* d, const uint32_t* a,
                                            uint32_t b0, uint32_t b1) {
    asm volatile(
        "mma.sync.aligned.m16n8k32.row.col.s32.s8.s8.s32 "
        "{%0,%1,%2,%3}, {%4,%5,%6,%7}, {%8,%9}, {%0,%1,%2,%3};"
        : "+r"(d[0]), "+r"(d[1]), "+r"(d[2]), "+r"(d[3])
        : "r"(a[0]), "r"(a[1]), "r"(a[2]), "r"(a[3]), "r"(b0), "r"(b1));
}

// ---------------- geometry ----------------------------------------------------
static constexpr int      NCHUNK      = 32;       // 4096 / 128
static constexpr uint32_t TILE_BYTES  = 16384;    // 128 rows x 128 k-bytes
static constexpr int      STAGES      = 4;
static constexpr uint32_t STAGE_BYTES = 3 * TILE_BYTES;   // A0 + A1 + B = 48KB
static constexpr uint32_t OFF_FULL    = 0;        // 4 x 8B
static constexpr uint32_t OFF_EMPTY   = 64;       // 4 x 8B
static constexpr uint32_t OFF_STAGE   = 1024;
static constexpr uint32_t SMEM_DYN    = OFF_STAGE + STAGES * STAGE_BYTES;  // 197632

// ---------------- prologue: quantize x (2 s8 levels) + rowsum + scale --------
__global__ void __launch_bounds__(256) prep_x_kernel(const float* __restrict__ x) {
    const int m = blockIdx.x;
    const int tid = threadIdx.x;
    const float4* row = (const float4*)(x + (size_t)m * 4096);
    float4 v[4];
    #pragma unroll
    for (int i = 0; i < 4; i++) v[i] = row[tid * 4 + i];

    float mx = 0.f, sm = 0.f;
    #pragma unroll
    for (int i = 0; i < 4; i++) {
        mx = fmaxf(mx, fmaxf(fmaxf(fabsf(v[i].x), fabsf(v[i].y)),
                             fmaxf(fabsf(v[i].z), fabsf(v[i].w))));
        sm += (v[i].x + v[i].y) + (v[i].z + v[i].w);
    }
    __shared__ float smax[256], ssum[256];
    smax[tid] = mx; ssum[tid] = sm;
    __syncthreads();
    for (int s = 128; s > 0; s >>= 1) {
        if (tid < s) {
            smax[tid] = fmaxf(smax[tid], smax[tid + s]);
            ssum[tid] += ssum[tid + s];
        }
        __syncthreads();
    }
    const float maxv = smax[0];
    const float inv  = (maxv > 0.f) ? 127.f / maxv : 0.f;

    uint32_t p1[4], p2[4];
    #pragma unroll
    for (int i = 0; i < 4; i++) {
        float e[4] = {v[i].x, v[i].y, v[i].z, v[i].w};
        uint32_t w1 = 0, w2 = 0;
        #pragma unroll
        for (int b = 0; b < 4; b++) {
            float r0 = e[b] * inv;
            int q1 = __float2int_rn(r0);
            int q2 = __float2int_rn((r0 - (float)q1) * 254.f);
            w1 |= (uint32_t)(q1 & 0xff) << (8 * b);
            w2 |= (uint32_t)(q2 & 0xff) << (8 * b);
        }
        p1[i] = w1; p2[i] = w2;
    }
    const uint32_t inrow = (uint32_t)((tid & 7) * 16);
    const uint32_t swzc  = inrow ^ (uint32_t)((m & 7) << 4);
    const size_t off = ((size_t)(m >> 7) * 32 + (size_t)(tid >> 3)) * TILE_BYTES
                     + (size_t)((m & 127) * 128) + swzc;
    *(uint4*)((char*)g_a0 + off) = make_uint4(p1[0], p1[1], p1[2], p1[3]);
    *(uint4*)((char*)g_a1 + off) = make_uint4(p2[0], p2[1], p2[2], p2[3]);
    if (tid == 0) {
        g_scale[m]  = (maxv > 0.f) ? maxv / 127.f : 0.f;
        g_rowsum[m] = ssum[0];
    }
}

// ---------------- prologue: sign(W) as s8 -------------------------------------
__global__ void __launch_bounds__(256) prep_w_kernel(const float* __restrict__ w) {
    const int n = blockIdx.x;
    const int tid = threadIdx.x;
    const float4* row = (const float4*)(w + (size_t)n * 4096);
    uint32_t p[4];
    #pragma unroll
    for (int i = 0; i < 4; i++) {
        float4 v = row[tid * 4 + i];
        float e[4] = {v.x, v.y, v.z, v.w};
        uint32_t wq = 0;
        #pragma unroll
        for (int b = 0; b < 4; b++) {
            int q = (e[b] > 0.f) ? 1 : ((e[b] < 0.f) ? -1 : 0);
            wq |= (uint32_t)(q & 0xff) << (8 * b);
        }
        p[i] = wq;
    }
    const uint32_t inrow = (uint32_t)((tid & 7) * 16);
    const uint32_t swzc  = inrow ^ (uint32_t)((n & 7) << 4);
    const size_t off = ((size_t)(n >> 7) * 32 + (size_t)(tid >> 3)) * TILE_BYTES
                     + (size_t)((n & 127) * 128) + swzc;
    *(uint4*)((char*)g_b + off) = make_uint4(p[0], p[1], p[2], p[3]);
}

// ---------------- main GEMM ----------------------------------------------------
// grid (32 ntile, 32 mtile), 512 threads: 16 compute warps (4M x 4N, 32x32 tile).
// Producer duties inlined into warp 0 lane 0 (self-issued 4-stage pipeline).
__global__ void __launch_bounds__(512, 1)
gemm_kernel(const float* __restrict__ wscale, const float* __restrict__ wbias,
            float* __restrict__ out) {
    extern __shared__ __align__(1024) char smem[];
    const uint32_t sb = smem_u32(smem);
    const int tid = threadIdx.x;
    const int wid = tid >> 5;
    const int lane = tid & 31;
    const int ntile = blockIdx.x;
    const int mtile = blockIdx.y;

    const char* pa0 = (const char*)g_a0 + (size_t)mtile * (32u * TILE_BYTES);
    const char* pa1 = (const char*)g_a1 + (size_t)mtile * (32u * TILE_BYTES);
    const char* pb  = (const char*)g_b  + (size_t)ntile * (32u * TILE_BYTES);

    if (tid == 0) {
        #pragma unroll
        for (int s = 0; s < STAGES; s++) {
            MBARRIER_INIT(sb + OFF_FULL  + 8u * s, 1);
            MBARRIER_INIT(sb + OFF_EMPTY + 8u * s, 16);
        }
    }
    __syncthreads();

    // prime the pipeline: issue chunks 0..3
    if (tid == 0) {
        #pragma unroll
        for (int s = 0; s < STAGES; s++) {
            uint32_t fb = sb + OFF_FULL + 8u * s;
            MBARRIER_EXPECT_TX(fb, STAGE_BYTES);
            uint32_t dst = sb + OFF_STAGE + (uint32_t)s * STAGE_BYTES;
            size_t co = (size_t)s * TILE_BYTES;
            bulk_g2s(dst,                  pa0 + co, TILE_BYTES, fb);
            bulk_g2s(dst + TILE_BYTES,     pa1 + co, TILE_BYTES, fb);
            bulk_g2s(dst + 2 * TILE_BYTES, pb  + co, TILE_BYTES, fb);
        }
    }

    // ---------------- per-warp tiling: 4(M) x 4(N), warp tile 32x32 -----------
    const int mw  = wid >> 2;         // 0..3
    const int nwp = wid & 3;          // 0..3
    const int rA = lane & 15;
    const uint32_t hb = (uint32_t)((lane >> 4) * 16);
    const uint32_t ph_sw = (uint32_t)((rA & 7) << 4);

    uint32_t rowA[2], rowB[2];
    #pragma unroll
    for (int t = 0; t < 2; t++) rowA[t] = (uint32_t)((mw * 32 + t * 16 + rA) * 128);
    #pragma unroll
    for (int j = 0; j < 2; j++) rowB[j] = (uint32_t)((nwp * 32 + j * 16 + rA) * 128);
    uint32_t colx[4];
    #pragma unroll
    for (int ks = 0; ks < 4; ks++) colx[ks] = ((uint32_t)(ks * 32) + hb) ^ ph_sw;

    int acc0[2][4][4];   // [t][j*2+n8][reg]
    int acc1[2][4][4];
    #pragma unroll
    for (int t = 0; t < 2; t++)
        #pragma unroll
        for (int u = 0; u < 4; u++)
            #pragma unroll
            for (int i = 0; i < 4; i++) { acc0[t][u][i] = 0; acc1[t][u][i] = 0; }

    for (int ch = 0; ch < NCHUNK; ch++) {
        const int st = ch & 3;
        const int ph = (ch >> 2) & 1;
        MBARRIER_WAIT_PARITY(sb + OFF_FULL + 8u * st, ph);
        const uint32_t SA0 = sb + OFF_STAGE + (uint32_t)st * STAGE_BYTES;
        const uint32_t SA1 = SA0 + TILE_BYTES;
        const uint32_t SB  = SA0 + 2 * TILE_BYTES;

        #pragma unroll
        for (int ks = 0; ks < 4; ks++) {
            uint32_t a0f[2][4], a1f[2][4], bf[2][4];
            #pragma unroll
            for (int t = 0; t < 2; t++) {
                ldsm4(a0f[t], SA0 + rowA[t] + colx[ks]);
                ldsm4(a1f[t], SA1 + rowA[t] + colx[ks]);
            }
            #pragma unroll
            for (int j = 0; j < 2; j++) ldsm4(bf[j], SB + rowB[j] + colx[ks]);

            #pragma unroll
            for (int t = 0; t < 2; t++) {
                #pragma unroll
                for (int j = 0; j < 2; j++) {
                    imma(acc0[t][2 * j],     a0f[t], bf[j][0], bf[j][2]);
                    imma(acc0[t][2 * j + 1], a0f[t], bf[j][1], bf[j][3]);
                    imma(acc1[t][2 * j],     a1f[t], bf[j][0], bf[j][2]);
                    imma(acc1[t][2 * j + 1], a1f[t], bf[j][1], bf[j][3]);
                }
            }
        }
        if (lane == 0) MBARRIER_ARRIVE(sb + OFF_EMPTY + 8u * st);
        // self-issued producer: refill this stage with chunk ch+4
        if (tid == 0 && ch + STAGES < NCHUNK) {
            MBARRIER_WAIT_PARITY_RELAXED(sb + OFF_EMPTY + 8u * st, ph);
            uint32_t fb = sb + OFF_FULL + 8u * st;
            MBARRIER_EXPECT_TX(fb, STAGE_BYTES);
            uint32_t dst = sb + OFF_STAGE + (uint32_t)st * STAGE_BYTES;
            size_t co = (size_t)(ch + STAGES) * TILE_BYTES;
            bulk_g2s(dst,                  pa0 + co, TILE_BYTES, fb);
            bulk_g2s(dst + TILE_BYTES,     pa1 + co, TILE_BYTES, fb);
            bulk_g2s(dst + 2 * TILE_BYTES, pb  + co, TILE_BYTES, fb);
        }
    }

    // ---------------- epilogue ----------------
    const float inv254 = 1.f / 254.f;
    const int lg = lane >> 2;           // 0..7
    const int lc = (lane & 3) * 2;      // 0,2,4,6
    const int nbase = ntile * 128 + nwp * 32 + lc;
    #pragma unroll
    for (int t = 0; t < 2; t++) {
        #pragma unroll
        for (int half = 0; half < 2; half++) {
            const int m = mtile * 128 + mw * 32 + t * 16 + lg + half * 8;
            const float alpha = g_scale[m];
            const float rs    = g_rowsum[m];
            float* orow = out + (size_t)m * 4096;
            const int i0 = half * 2, i1 = half * 2 + 1;
            #pragma unroll
            for (int u = 0; u < 4; u++) {
                const int n = nbase + u * 8;
                float v0 = (float)acc0[t][u][i0] + (float)acc1[t][u][i0] * inv254;
                float v1 = (float)acc0[t][u][i1] + (float)acc1[t][u][i1] * inv254;
                float2 o;
                o.x = __ldg(wscale + n)     * (alpha * v0) + __ldg(wbias + n)     * rs;
                o.y = __ldg(wscale + n + 1) * (alpha * v1) + __ldg(wbias + n + 1) * rs;
                *(float2*)(orow + n) = o;
            }
        }
    }
}

// ---------------- launch --------------------------------------------------------
extern "C" void kernel_launch(void* const* d_in, const int* in_sizes, int n_in,
                              void* d_out, int out_size) {
    (void)in_sizes; (void)n_in; (void)out_size;
    const float* x      = (const float*)d_in[0];   // [2,2048,4096]
    const float* weight = (const float*)d_in[1];   // [4096,4096]
    const float* wscale = (const float*)d_in[2];   // [4096,1]
    const float* wbias  = (const float*)d_in[3];   // [4096,1]
    float* out = (float*)d_out;

    cudaFuncSetAttribute(gemm_kernel, cudaFuncAttributeMaxDynamicSharedMemorySize,
                         (int)SMEM_DYN);

    prep_x_kernel<<<4096, 256>>>(x);
    prep_w_kernel<<<4096, 256>>>(weight);
    dim3 grid(32, 32);
    gemm_kernel<<<grid, 512, SMEM_DYN>>>(wscale, wbias, out);
}